// round 3
// baseline (speedup 1.0000x reference)
#include <cuda_runtime.h>
#include <cstdint>

#define NN    10000
#define NF    512
#define NH    32
#define NC    16
#define EMAX  360000

typedef unsigned long long ull;

// ---- scratch (static device globals; no allocation allowed) ----
__device__ float g_xw1a[NN * NH];    // x @ W1 (k-half 0)
__device__ float g_xw1b[NN * NH];    // x @ W1 (k-half 1)
__device__ float g_xw1 [NN * NH];    // sum
__device__ float g_h  [NN * NH];     // relu(A_hat @ xw1)
__device__ float g_hw2[NN * NC];     // h @ W2
__device__ float g_z  [NN * NC];     // A_hat @ hw2
__device__ int   g_counts[NN];
__device__ int   g_rowstart[NN + 1];
__device__ int   g_cursor[NN];
__device__ int   g_col[EMAX];
__device__ float g_val[EMAX];

__device__ __forceinline__ ull fma2(ull a, ull b, ull c) {
    ull d;
    asm("fma.rn.f32x2 %0, %1, %2, %3;" : "=l"(d) : "l"(a), "l"(b), "l"(c));
    return d;
}
__device__ __forceinline__ float2 unpack2(ull v) {
    float2 u;
    asm("mov.b64 {%0, %1}, %2;" : "=f"(u.x), "=f"(u.y) : "l"(v));
    return u;
}
__device__ __forceinline__ float sigmoidf(float v) {
    return __fdividef(1.f, 1.f + __expf(-v));
}

// ---------------------------------------------------------------
__global__ void k_init_counts() {
    int i = blockIdx.x * blockDim.x + threadIdx.x;
    if (i < NN) g_counts[i] = 0;
}

__global__ void k_hist(const int* __restrict__ dst, int E) {
    int e = blockIdx.x * blockDim.x + threadIdx.x;
    if (e < E) atomicAdd(&g_counts[dst[e]], 1);
}

__global__ void k_scan() {
    __shared__ int sums[1024];
    const int t = threadIdx.x;
    int loc[10];
    int s = 0;
#pragma unroll
    for (int j = 0; j < 10; j++) {
        int i = t * 10 + j;
        int c = (i < NN) ? g_counts[i] : 0;
        loc[j] = s;
        s += c;
    }
    sums[t] = s;
    __syncthreads();
    for (int off = 1; off < 1024; off <<= 1) {
        int v = (t >= off) ? sums[t - off] : 0;
        __syncthreads();
        sums[t] += v;
        __syncthreads();
    }
    int base = (t > 0) ? sums[t - 1] : 0;
#pragma unroll
    for (int j = 0; j < 10; j++) {
        int i = t * 10 + j;
        if (i < NN) {
            int off = base + loc[j];
            g_rowstart[i] = off;
            g_cursor[i]   = off;
        }
    }
    if (t == 1023) g_rowstart[NN] = sums[1023];
}

__global__ void k_scatter(const int* __restrict__ src, const int* __restrict__ dst,
                          const float* __restrict__ w, int E) {
    int e = blockIdx.x * blockDim.x + threadIdx.x;
    if (e < E) {
        int d = dst[e];
        int p = atomicAdd(&g_cursor[d], 1);
        g_col[p] = src[e];
        g_val[p] = w[e];
    }
}

// ---------------------------------------------------------------
// gemm1: xw1_half = x[:, khalf*256:(khalf+1)*256] @ W1[khalf*256:...,:]
// BM=128, BN=32, BK=32, 256 threads, f32x2 packed FMA (row pairs).
__global__ __launch_bounds__(256) void k_gemm1(const float* __restrict__ x,
                                               const float* __restrict__ W1) {
    __shared__ float  xsT[32][132];      // k-major, padded
    __shared__ float2 ws2[32][32];       // duplicated W
    const int tid = threadIdx.x;
    const int row0 = blockIdx.x * 128;
    const int kbase = blockIdx.y * 256;
    float* outbuf = blockIdx.y ? g_xw1b : g_xw1a;

    const int tx = tid & 7;    // 8 col-groups of 4
    const int ty = tid >> 3;   // 32 row-groups of 4

    ull acc[2][4] = {};

    for (int kc = 0; kc < 8; kc++) {
        int k0 = kbase + kc * 32;
        // load x tile transposed: 1024 float4-equivalent pieces
#pragma unroll
        for (int j = 0; j < 4; j++) {
            int f   = tid + 256 * j;
            int row = f >> 3;
            int kq  = f & 7;
            int gr  = row0 + row;
            float4 v = make_float4(0.f, 0.f, 0.f, 0.f);
            if (gr < NN) v = *(const float4*)&x[(size_t)gr * NF + k0 + kq * 4];
            xsT[kq * 4 + 0][row] = v.x;
            xsT[kq * 4 + 1][row] = v.y;
            xsT[kq * 4 + 2][row] = v.z;
            xsT[kq * 4 + 3][row] = v.w;
        }
        // load W tile duplicated
#pragma unroll
        for (int j = 0; j < 4; j++) {
            int f = tid + 256 * j;
            int r = f >> 5;
            int c = f & 31;
            float v = W1[(k0 + r) * NH + c];
            ws2[r][c] = make_float2(v, v);
        }
        __syncthreads();
#pragma unroll
        for (int kk = 0; kk < 32; kk++) {
            ulonglong2 a  = *(ulonglong2*)&xsT[kk][ty * 4];
            ulonglong2 b0 = *(ulonglong2*)&ws2[kk][tx * 4];
            ulonglong2 b1 = *(ulonglong2*)&ws2[kk][tx * 4 + 2];
            acc[0][0] = fma2(a.x, b0.x, acc[0][0]);
            acc[0][1] = fma2(a.x, b0.y, acc[0][1]);
            acc[0][2] = fma2(a.x, b1.x, acc[0][2]);
            acc[0][3] = fma2(a.x, b1.y, acc[0][3]);
            acc[1][0] = fma2(a.y, b0.x, acc[1][0]);
            acc[1][1] = fma2(a.y, b0.y, acc[1][1]);
            acc[1][2] = fma2(a.y, b1.x, acc[1][2]);
            acc[1][3] = fma2(a.y, b1.y, acc[1][3]);
        }
        __syncthreads();
    }
    // store: rows ty*4 + {0,1} from acc[0] (lo/hi), +{2,3} from acc[1]
#pragma unroll
    for (int p = 0; p < 2; p++) {
        float2 c0v = unpack2(acc[p][0]);
        float2 c1v = unpack2(acc[p][1]);
        float2 c2v = unpack2(acc[p][2]);
        float2 c3v = unpack2(acc[p][3]);
        int gr0 = row0 + ty * 4 + p * 2;
        if (gr0 < NN) {
            float4 o = make_float4(c0v.x, c1v.x, c2v.x, c3v.x);
            *(float4*)&outbuf[gr0 * NH + tx * 4] = o;
        }
        if (gr0 + 1 < NN) {
            float4 o = make_float4(c0v.y, c1v.y, c2v.y, c3v.y);
            *(float4*)&outbuf[(gr0 + 1) * NH + tx * 4] = o;
        }
    }
}

// add the two k-halves
__global__ void k_add() {
    int i = blockIdx.x * blockDim.x + threadIdx.x;
    if (i < NN * NH / 4) {
        float4 a = *(float4*)&g_xw1a[i * 4];
        float4 b = *(float4*)&g_xw1b[i * 4];
        float4 o = make_float4(a.x + b.x, a.y + b.y, a.z + b.z, a.w + b.w);
        *(float4*)&g_xw1[i * 4] = o;
    }
}

// ---------------------------------------------------------------
// spmm1: h = relu(A_hat @ xw1). Warp per row; uniform col/val loads (no shuffles).
__global__ void k_spmm1() {
    int warp = (blockIdx.x * blockDim.x + threadIdx.x) >> 5;
    int l = threadIdx.x & 31;
    if (warp >= NN) return;
    int start = g_rowstart[warp];
    int end   = g_rowstart[warp + 1];
    float acc = 0.f;
    int e = start;
    for (; e + 3 < end; e += 4) {
        int   s0 = g_col[e + 0], s1 = g_col[e + 1], s2 = g_col[e + 2], s3 = g_col[e + 3];
        float w0 = g_val[e + 0], w1 = g_val[e + 1], w2 = g_val[e + 2], w3 = g_val[e + 3];
        acc += w0 * g_xw1[s0 * NH + l];
        acc += w1 * g_xw1[s1 * NH + l];
        acc += w2 * g_xw1[s2 * NH + l];
        acc += w3 * g_xw1[s3 * NH + l];
    }
    for (; e < end; e++) {
        acc += g_val[e] * g_xw1[g_col[e] * NH + l];
    }
    g_h[warp * NH + l] = fmaxf(acc, 0.f);
}

// hw2 = h @ W2 (thread per row)
__global__ void k_gemm2(const float* __restrict__ W2) {
    __shared__ float w2s[NH * NC];
    const int tid = threadIdx.x;
    for (int i = tid; i < NH * NC; i += blockDim.x) w2s[i] = W2[i];
    __syncthreads();
    int row = blockIdx.x * blockDim.x + tid;
    if (row >= NN) return;
    float acc[NC] = {};
#pragma unroll
    for (int l = 0; l < NH; l++) {
        float hv = g_h[row * NH + l];
#pragma unroll
        for (int c = 0; c < NC; c++) acc[c] += hv * w2s[l * NC + c];
    }
#pragma unroll
    for (int q = 0; q < NC; q += 4) {
        float4 o = make_float4(acc[q], acc[q + 1], acc[q + 2], acc[q + 3]);
        *(float4*)&g_z[0] ; // placeholder avoided
        *(float4*)&g_hw2[row * NC + q] = o;
    }
}

// spmm2: z = A_hat @ hw2. Warp per row; half-warps process alternating edges.
__global__ void k_spmm2() {
    int warp = (blockIdx.x * blockDim.x + threadIdx.x) >> 5;
    int l = threadIdx.x & 31;
    if (warp >= NN) return;
    int f    = l & 15;
    int half = l >> 4;
    int start = g_rowstart[warp];
    int end   = g_rowstart[warp + 1];
    float acc = 0.f;
    for (int e = start + half; e < end; e += 2) {
        int   s = g_col[e];
        float w = g_val[e];
        acc += w * g_hw2[s * NC + f];
    }
    acc += __shfl_xor_sync(0xffffffffu, acc, 16);
    if (l < 16) g_z[warp * NC + l] = acc;
}

// ---------------------------------------------------------------
// decode: out = sigmoid(z @ z^T). 128x128 tile, 256 threads, 8x8 microtile,
// packed f32x2 FMA (row pairs), duplicated column operand in smem.
__global__ __launch_bounds__(256, 2) void k_decode(float* __restrict__ out) {
    __shared__ float  zr [NC][128];
    __shared__ float2 zc2[NC][128];
    const int tid = threadIdx.x;
    const int r0 = blockIdx.y * 128;
    const int c0 = blockIdx.x * 128;

    // load 128 rows + 128 cols of z (16 feats each)
#pragma unroll
    for (int j = 0; j < 2; j++) {
        int f   = tid + 256 * j;   // 0..511
        int row = f >> 2;          // 0..127
        int kq  = f & 3;
        int gr = r0 + row;
        float4 v = (gr < NN) ? *(const float4*)&g_z[gr * NC + kq * 4]
                             : make_float4(0.f, 0.f, 0.f, 0.f);
        zr[kq * 4 + 0][row] = v.x; zr[kq * 4 + 1][row] = v.y;
        zr[kq * 4 + 2][row] = v.z; zr[kq * 4 + 3][row] = v.w;
        int gc = c0 + row;
        float4 w = (gc < NN) ? *(const float4*)&g_z[gc * NC + kq * 4]
                             : make_float4(0.f, 0.f, 0.f, 0.f);
        zc2[kq * 4 + 0][row] = make_float2(w.x, w.x);
        zc2[kq * 4 + 1][row] = make_float2(w.y, w.y);
        zc2[kq * 4 + 2][row] = make_float2(w.z, w.z);
        zc2[kq * 4 + 3][row] = make_float2(w.w, w.w);
    }
    __syncthreads();

    const int tx = tid & 15;   // 16 col groups: cols tx*4..+3 and 64+tx*4..+3
    const int ty = tid >> 4;   // 16 row groups of 8 rows

    ull acc[4][8] = {};
#pragma unroll
    for (int k = 0; k < NC; k++) {
        ulonglong2 a0 = *(ulonglong2*)&zr[k][ty * 8];       // rows +0..3 (2 pairs)
        ulonglong2 a1 = *(ulonglong2*)&zr[k][ty * 8 + 4];   // rows +4..7
        ull A[4] = {a0.x, a0.y, a1.x, a1.y};
        ulonglong2 b0 = *(ulonglong2*)&zc2[k][tx * 4];
        ulonglong2 b1 = *(ulonglong2*)&zc2[k][tx * 4 + 2];
        ulonglong2 b2 = *(ulonglong2*)&zc2[k][64 + tx * 4];
        ulonglong2 b3 = *(ulonglong2*)&zc2[k][64 + tx * 4 + 2];
        ull B[8] = {b0.x, b0.y, b1.x, b1.y, b2.x, b2.y, b3.x, b3.y};
#pragma unroll
        for (int p = 0; p < 4; p++)
#pragma unroll
            for (int j = 0; j < 8; j++)
                acc[p][j] = fma2(A[p], B[j], acc[p][j]);
    }

    const int gc0 = c0 + tx * 4;
    const int gc1 = c0 + 64 + tx * 4;
#pragma unroll
    for (int p = 0; p < 4; p++) {
        float2 u[8];
#pragma unroll
        for (int j = 0; j < 8; j++) u[j] = unpack2(acc[p][j]);
#pragma unroll
        for (int h = 0; h < 2; h++) {
            int gr = r0 + ty * 8 + 2 * p + h;
            if (gr >= NN) continue;
            float v0 = h ? u[0].y : u[0].x;
            float v1 = h ? u[1].y : u[1].x;
            float v2 = h ? u[2].y : u[2].x;
            float v3 = h ? u[3].y : u[3].x;
            float v4 = h ? u[4].y : u[4].x;
            float v5 = h ? u[5].y : u[5].x;
            float v6 = h ? u[6].y : u[6].x;
            float v7 = h ? u[7].y : u[7].x;
            if (gc0 < NN) {
                float4 o = make_float4(sigmoidf(v0), sigmoidf(v1),
                                       sigmoidf(v2), sigmoidf(v3));
                *(float4*)&out[(size_t)gr * NN + gc0] = o;
            }
            if (gc1 < NN) {
                float4 o = make_float4(sigmoidf(v4), sigmoidf(v5),
                                       sigmoidf(v6), sigmoidf(v7));
                *(float4*)&out[(size_t)gr * NN + gc1] = o;
            }
        }
    }
}

// ---------------------------------------------------------------
extern "C" void kernel_launch(void* const* d_in, const int* in_sizes, int n_in,
                              void* d_out, int out_size) {
    const float* x   = (const float*)d_in[0];   // [10000, 512]
    const float* W1  = (const float*)d_in[1];   // [512, 32]
    const float* W2  = (const float*)d_in[2];   // [32, 16]
    const float* ew  = (const float*)d_in[3];   // [E]
    const int*   src = (const int*)d_in[4];     // [E]
    const int*   dst = (const int*)d_in[5];     // [E]
    float* out = (float*)d_out;
    const int E = in_sizes[3];

    const int eb = (E + 255) / 256;

    k_init_counts<<<(NN + 255) / 256, 256>>>();
    k_hist<<<eb, 256>>>(dst, E);
    k_scan<<<1, 1024>>>();
    k_scatter<<<eb, 256>>>(src, dst, ew, E);

    dim3 g1((NN + 127) / 128, 2);
    k_gemm1<<<g1, 256>>>(x, W1);
    k_add<<<(NN * NH / 4 + 255) / 256, 256>>>();
    k_spmm1<<<(NN * 32 + 255) / 256, 256>>>();
    k_gemm2<<<(NN + 255) / 256, 256>>>(W2);
    k_spmm2<<<(NN * 32 + 255) / 256, 256>>>();

    dim3 grid((NN + 127) / 128, (NN + 127) / 128);
    k_decode<<<grid, 256>>>(out);
}

// round 4
// speedup vs baseline: 1.0017x; 1.0017x over previous
#include <cuda_runtime.h>
#include <cstdint>

#define NN    10000
#define NF    512
#define NH    32
#define NC    16
#define EMAX  360000

typedef unsigned long long ull;

// ---- scratch (static device globals; no allocation allowed) ----
__device__ float g_xw1a[NN * NH];    // x @ W1 (k-half 0)
__device__ float g_xw1b[NN * NH];    // x @ W1 (k-half 1)
__device__ float g_xw1 [NN * NH];    // sum
__device__ float g_h  [NN * NH];     // relu(A_hat @ xw1)
__device__ float g_hw2[NN * NC];     // h @ W2
__device__ float g_z  [NN * NC];     // A_hat @ hw2
__device__ int   g_counts[NN];
__device__ int   g_rowstart[NN + 1];
__device__ int   g_cursor[NN];
__device__ ull   g_cv[EMAX];         // packed (val<<32 | col)

__device__ __forceinline__ ull fma2(ull a, ull b, ull c) {
    ull d;
    asm("fma.rn.f32x2 %0, %1, %2, %3;" : "=l"(d) : "l"(a), "l"(b), "l"(c));
    return d;
}
__device__ __forceinline__ float2 unpack2(ull v) {
    float2 u;
    asm("mov.b64 {%0, %1}, %2;" : "=f"(u.x), "=f"(u.y) : "l"(v));
    return u;
}
__device__ __forceinline__ float sigmoidf(float v) {
    return __fdividef(1.f, 1.f + __expf(-v));
}

// ---------------------------------------------------------------
__global__ void k_init_counts() {
    int i = blockIdx.x * blockDim.x + threadIdx.x;
    if (i < NN) g_counts[i] = 0;
}

__global__ void k_hist(const int* __restrict__ dst, int E) {
    int e = blockIdx.x * blockDim.x + threadIdx.x;
    if (e < E) atomicAdd(&g_counts[dst[e]], 1);
}

__global__ void k_scan() {
    __shared__ int sums[1024];
    const int t = threadIdx.x;
    int loc[10];
    int s = 0;
#pragma unroll
    for (int j = 0; j < 10; j++) {
        int i = t * 10 + j;
        int c = (i < NN) ? g_counts[i] : 0;
        loc[j] = s;
        s += c;
    }
    sums[t] = s;
    __syncthreads();
    for (int off = 1; off < 1024; off <<= 1) {
        int v = (t >= off) ? sums[t - off] : 0;
        __syncthreads();
        sums[t] += v;
        __syncthreads();
    }
    int base = (t > 0) ? sums[t - 1] : 0;
#pragma unroll
    for (int j = 0; j < 10; j++) {
        int i = t * 10 + j;
        if (i < NN) {
            int off = base + loc[j];
            g_rowstart[i] = off;
            g_cursor[i]   = off;
        }
    }
    if (t == 1023) g_rowstart[NN] = sums[1023];
}

__global__ void k_scatter(const int* __restrict__ src, const int* __restrict__ dst,
                          const float* __restrict__ w, int E) {
    int e = blockIdx.x * blockDim.x + threadIdx.x;
    if (e < E) {
        int d = dst[e];
        int p = atomicAdd(&g_cursor[d], 1);
        ull cv = ((ull)__float_as_uint(w[e]) << 32) | (unsigned)src[e];
        g_cv[p] = cv;
    }
}

// ---------------------------------------------------------------
// gemm1: xw1_half = x[:, khalf*256:(khalf+1)*256] @ W1[khalf*256:...,:]
// BM=128, BN=32, BK=32, 256 threads, f32x2 packed FMA (row pairs).
__global__ __launch_bounds__(256) void k_gemm1(const float* __restrict__ x,
                                               const float* __restrict__ W1) {
    __shared__ float  xsT[32][132];      // k-major, padded
    __shared__ float2 ws2[32][32];       // duplicated W
    const int tid = threadIdx.x;
    const int row0 = blockIdx.x * 128;
    const int kbase = blockIdx.y * 256;
    float* outbuf = blockIdx.y ? g_xw1b : g_xw1a;

    const int tx = tid & 7;    // 8 col-groups of 4
    const int ty = tid >> 3;   // 32 row-groups of 4

    ull acc[2][4] = {};

    for (int kc = 0; kc < 8; kc++) {
        int k0 = kbase + kc * 32;
#pragma unroll
        for (int j = 0; j < 4; j++) {
            int f   = tid + 256 * j;
            int row = f >> 3;
            int kq  = f & 7;
            int gr  = row0 + row;
            float4 v = make_float4(0.f, 0.f, 0.f, 0.f);
            if (gr < NN) v = *(const float4*)&x[(size_t)gr * NF + k0 + kq * 4];
            xsT[kq * 4 + 0][row] = v.x;
            xsT[kq * 4 + 1][row] = v.y;
            xsT[kq * 4 + 2][row] = v.z;
            xsT[kq * 4 + 3][row] = v.w;
        }
#pragma unroll
        for (int j = 0; j < 4; j++) {
            int f = tid + 256 * j;
            int r = f >> 5;
            int c = f & 31;
            float v = W1[(k0 + r) * NH + c];
            ws2[r][c] = make_float2(v, v);
        }
        __syncthreads();
#pragma unroll
        for (int kk = 0; kk < 32; kk++) {
            ulonglong2 a  = *(ulonglong2*)&xsT[kk][ty * 4];
            ulonglong2 b0 = *(ulonglong2*)&ws2[kk][tx * 4];
            ulonglong2 b1 = *(ulonglong2*)&ws2[kk][tx * 4 + 2];
            acc[0][0] = fma2(a.x, b0.x, acc[0][0]);
            acc[0][1] = fma2(a.x, b0.y, acc[0][1]);
            acc[0][2] = fma2(a.x, b1.x, acc[0][2]);
            acc[0][3] = fma2(a.x, b1.y, acc[0][3]);
            acc[1][0] = fma2(a.y, b0.x, acc[1][0]);
            acc[1][1] = fma2(a.y, b0.y, acc[1][1]);
            acc[1][2] = fma2(a.y, b1.x, acc[1][2]);
            acc[1][3] = fma2(a.y, b1.y, acc[1][3]);
        }
        __syncthreads();
    }
#pragma unroll
    for (int p = 0; p < 2; p++) {
        float2 c0v = unpack2(acc[p][0]);
        float2 c1v = unpack2(acc[p][1]);
        float2 c2v = unpack2(acc[p][2]);
        float2 c3v = unpack2(acc[p][3]);
        int gr0 = row0 + ty * 4 + p * 2;
        if (gr0 < NN) {
            float4 o = make_float4(c0v.x, c1v.x, c2v.x, c3v.x);
            *(float4*)&outbuf[gr0 * NH + tx * 4] = o;
        }
        if (gr0 + 1 < NN) {
            float4 o = make_float4(c0v.y, c1v.y, c2v.y, c3v.y);
            *(float4*)&outbuf[(gr0 + 1) * NH + tx * 4] = o;
        }
    }
}

// add the two k-halves
__global__ void k_add() {
    int i = blockIdx.x * blockDim.x + threadIdx.x;
    if (i < NN * NH / 4) {
        float4 a = *(float4*)&g_xw1a[i * 4];
        float4 b = *(float4*)&g_xw1b[i * 4];
        float4 o = make_float4(a.x + b.x, a.y + b.y, a.z + b.z, a.w + b.w);
        *(float4*)&g_xw1[i * 4] = o;
    }
}

// ---------------------------------------------------------------
// spmm1: h = relu(A_hat @ xw1). Warp per row; uniform packed cv loads.
__global__ void k_spmm1() {
    int warp = (blockIdx.x * blockDim.x + threadIdx.x) >> 5;
    int l = threadIdx.x & 31;
    if (warp >= NN) return;
    int start = g_rowstart[warp];
    int end   = g_rowstart[warp + 1];
    float acc = 0.f;
    int e = start;
    for (; e + 3 < end; e += 4) {
        ull cv0 = g_cv[e + 0], cv1 = g_cv[e + 1], cv2 = g_cv[e + 2], cv3 = g_cv[e + 3];
        int s0 = (int)(unsigned)cv0, s1 = (int)(unsigned)cv1;
        int s2 = (int)(unsigned)cv2, s3 = (int)(unsigned)cv3;
        float w0 = __uint_as_float((unsigned)(cv0 >> 32));
        float w1 = __uint_as_float((unsigned)(cv1 >> 32));
        float w2 = __uint_as_float((unsigned)(cv2 >> 32));
        float w3 = __uint_as_float((unsigned)(cv3 >> 32));
        acc += w0 * g_xw1[s0 * NH + l];
        acc += w1 * g_xw1[s1 * NH + l];
        acc += w2 * g_xw1[s2 * NH + l];
        acc += w3 * g_xw1[s3 * NH + l];
    }
    for (; e < end; e++) {
        ull cv = g_cv[e];
        int s = (int)(unsigned)cv;
        float w = __uint_as_float((unsigned)(cv >> 32));
        acc += w * g_xw1[s * NH + l];
    }
    g_h[warp * NH + l] = fmaxf(acc, 0.f);
}

// hw2 = h @ W2 (thread per row)
__global__ void k_gemm2(const float* __restrict__ W2) {
    __shared__ float w2s[NH * NC];
    const int tid = threadIdx.x;
    for (int i = tid; i < NH * NC; i += blockDim.x) w2s[i] = W2[i];
    __syncthreads();
    int row = blockIdx.x * blockDim.x + tid;
    if (row >= NN) return;
    float acc[NC] = {};
#pragma unroll
    for (int l = 0; l < NH; l++) {
        float hv = g_h[row * NH + l];
#pragma unroll
        for (int c = 0; c < NC; c++) acc[c] += hv * w2s[l * NC + c];
    }
#pragma unroll
    for (int q = 0; q < NC; q += 4) {
        float4 o = make_float4(acc[q], acc[q + 1], acc[q + 2], acc[q + 3]);
        *(float4*)&g_hw2[row * NC + q] = o;
    }
}

// spmm2: z = A_hat @ hw2. Warp per row; half-warps process alternating edges.
__global__ void k_spmm2() {
    int warp = (blockIdx.x * blockDim.x + threadIdx.x) >> 5;
    int l = threadIdx.x & 31;
    if (warp >= NN) return;
    int f    = l & 15;
    int half = l >> 4;
    int start = g_rowstart[warp];
    int end   = g_rowstart[warp + 1];
    float acc = 0.f;
    for (int e = start + half; e < end; e += 2) {
        ull cv = g_cv[e];
        int s = (int)(unsigned)cv;
        float w = __uint_as_float((unsigned)(cv >> 32));
        acc += w * g_hw2[s * NC + f];
    }
    acc += __shfl_xor_sync(0xffffffffu, acc, 16);
    if (l < 16) g_z[warp * NC + l] = acc;
}

// ---------------------------------------------------------------
// decode: out = sigmoid(z @ z^T). 128x64 tile, 256 threads, 8x4 microtile,
// packed f32x2 FMA (row pairs), duplicated column operand in smem.
// acc = 16 ull = 32 regs -> no spills (the R2 8x8 version spilled).
__global__ __launch_bounds__(256) void k_decode(float* __restrict__ out) {
    __shared__ float  zr [NC][132];   // padded: conflict-free stores, 16B-aligned rows
    __shared__ float2 zc2[NC][66];
    const int tid = threadIdx.x;
    const int r0 = blockIdx.y * 128;
    const int c0 = blockIdx.x * 64;

    // load 128 rows of z into zr (k-major)
#pragma unroll
    for (int j = 0; j < 2; j++) {
        int f   = tid + 256 * j;   // 0..511
        int row = f >> 2;          // 0..127
        int kq  = f & 3;
        int gr = r0 + row;
        float4 v = (gr < NN) ? *(const float4*)&g_z[gr * NC + kq * 4]
                             : make_float4(0.f, 0.f, 0.f, 0.f);
        zr[kq * 4 + 0][row] = v.x; zr[kq * 4 + 1][row] = v.y;
        zr[kq * 4 + 2][row] = v.z; zr[kq * 4 + 3][row] = v.w;
    }
    // load 64 cols of z into zc2, duplicated (v, v)
    {
        int row = tid >> 2;        // 0..63
        int kq  = tid & 3;
        int gc = c0 + row;
        float4 w = (gc < NN) ? *(const float4*)&g_z[gc * NC + kq * 4]
                             : make_float4(0.f, 0.f, 0.f, 0.f);
        zc2[kq * 4 + 0][row] = make_float2(w.x, w.x);
        zc2[kq * 4 + 1][row] = make_float2(w.y, w.y);
        zc2[kq * 4 + 2][row] = make_float2(w.z, w.z);
        zc2[kq * 4 + 3][row] = make_float2(w.w, w.w);
    }
    __syncthreads();

    const int tx = tid & 15;   // 16 col groups of 4 cols
    const int ty = tid >> 4;   // 16 row groups of 8 rows (4 pairs)

    ull acc[4][4] = {};
#pragma unroll
    for (int k = 0; k < NC; k++) {
        ulonglong2 a0 = *(ulonglong2*)&zr[k][ty * 8];       // row pairs 0,1
        ulonglong2 a1 = *(ulonglong2*)&zr[k][ty * 8 + 4];   // row pairs 2,3
        ulonglong2 b0 = *(ulonglong2*)&zc2[k][tx * 4];      // cols 0,1 (dup)
        ulonglong2 b1 = *(ulonglong2*)&zc2[k][tx * 4 + 2];  // cols 2,3 (dup)
        acc[0][0] = fma2(a0.x, b0.x, acc[0][0]);
        acc[0][1] = fma2(a0.x, b0.y, acc[0][1]);
        acc[0][2] = fma2(a0.x, b1.x, acc[0][2]);
        acc[0][3] = fma2(a0.x, b1.y, acc[0][3]);
        acc[1][0] = fma2(a0.y, b0.x, acc[1][0]);
        acc[1][1] = fma2(a0.y, b0.y, acc[1][1]);
        acc[1][2] = fma2(a0.y, b1.x, acc[1][2]);
        acc[1][3] = fma2(a0.y, b1.y, acc[1][3]);
        acc[2][0] = fma2(a1.x, b0.x, acc[2][0]);
        acc[2][1] = fma2(a1.x, b0.y, acc[2][1]);
        acc[2][2] = fma2(a1.x, b1.x, acc[2][2]);
        acc[2][3] = fma2(a1.x, b1.y, acc[2][3]);
        acc[3][0] = fma2(a1.y, b0.x, acc[3][0]);
        acc[3][1] = fma2(a1.y, b0.y, acc[3][1]);
        acc[3][2] = fma2(a1.y, b1.x, acc[3][2]);
        acc[3][3] = fma2(a1.y, b1.y, acc[3][3]);
    }

    const int gc0 = c0 + tx * 4;
    if (gc0 < NN) {
#pragma unroll
        for (int p = 0; p < 4; p++) {
            float2 u0 = unpack2(acc[p][0]);
            float2 u1 = unpack2(acc[p][1]);
            float2 u2 = unpack2(acc[p][2]);
            float2 u3 = unpack2(acc[p][3]);
            int gr = r0 + ty * 8 + 2 * p;
            if (gr < NN) {
                float4 o = make_float4(sigmoidf(u0.x), sigmoidf(u1.x),
                                       sigmoidf(u2.x), sigmoidf(u3.x));
                *(float4*)&out[(size_t)gr * NN + gc0] = o;
            }
            if (gr + 1 < NN) {
                float4 o = make_float4(sigmoidf(u0.y), sigmoidf(u1.y),
                                       sigmoidf(u2.y), sigmoidf(u3.y));
                *(float4*)&out[(size_t)(gr + 1) * NN + gc0] = o;
            }
        }
    }
}

// ---------------------------------------------------------------
extern "C" void kernel_launch(void* const* d_in, const int* in_sizes, int n_in,
                              void* d_out, int out_size) {
    const float* x   = (const float*)d_in[0];   // [10000, 512]
    const float* W1  = (const float*)d_in[1];   // [512, 32]
    const float* W2  = (const float*)d_in[2];   // [32, 16]
    const float* ew  = (const float*)d_in[3];   // [E]
    const int*   src = (const int*)d_in[4];     // [E]
    const int*   dst = (const int*)d_in[5];     // [E]
    float* out = (float*)d_out;
    const int E = in_sizes[3];

    const int eb = (E + 255) / 256;

    k_init_counts<<<(NN + 255) / 256, 256>>>();
    k_hist<<<eb, 256>>>(dst, E);
    k_scan<<<1, 1024>>>();
    k_scatter<<<eb, 256>>>(src, dst, ew, E);

    dim3 g1((NN + 127) / 128, 2);
    k_gemm1<<<g1, 256>>>(x, W1);
    k_add<<<(NN * NH / 4 + 255) / 256, 256>>>();
    k_spmm1<<<(NN * 32 + 255) / 256, 256>>>();
    k_gemm2<<<(NN + 255) / 256, 256>>>(W2);
    k_spmm2<<<(NN * 32 + 255) / 256, 256>>>();

    dim3 grid((NN + 63) / 64, (NN + 127) / 128);
    k_decode<<<grid, 256>>>(out);
}

// round 5
// speedup vs baseline: 1.3934x; 1.3910x over previous
#include <cuda_runtime.h>
#include <cstdint>

#define NN    10000
#define NF    512
#define NH    32
#define NC    16
#define EMAX  360000
#define NT64  157                    // ceil(10000/64)
#define NTRI  (NT64 * (NT64 + 1) / 2)

typedef unsigned long long ull;

// ---- scratch (static device globals; no allocation allowed) ----
__device__ float g_xw1p[4 * NN * NH];  // x @ W1 partials (4 K-chunks)
__device__ float g_xw1 [NN * NH];      // sum
__device__ float g_h   [NN * NH];      // relu(A_hat @ xw1)
__device__ float g_hw2 [NN * NC];      // h @ W2
__device__ float g_z   [NN * NC];      // A_hat @ hw2
__device__ int   g_counts[NN];
__device__ int   g_rowstart[NN + 1];
__device__ int   g_cursor[NN];
__device__ ull   g_cv[EMAX];           // packed (val<<32 | col)

__device__ __forceinline__ float sigmoidf(float v) {
    return __fdividef(1.f, 1.f + __expf(-v));
}

// ---------------------------------------------------------------
__global__ void k_init_counts() {
    int i = blockIdx.x * blockDim.x + threadIdx.x;
    if (i < NN) g_counts[i] = 0;
}

__global__ void k_hist(const int* __restrict__ dst, int E) {
    int e = blockIdx.x * blockDim.x + threadIdx.x;
    if (e < E) atomicAdd(&g_counts[dst[e]], 1);
}

__global__ void k_scan() {
    __shared__ int sums[1024];
    const int t = threadIdx.x;
    int loc[10];
    int s = 0;
#pragma unroll
    for (int j = 0; j < 10; j++) {
        int i = t * 10 + j;
        int c = (i < NN) ? g_counts[i] : 0;
        loc[j] = s;
        s += c;
    }
    sums[t] = s;
    __syncthreads();
    for (int off = 1; off < 1024; off <<= 1) {
        int v = (t >= off) ? sums[t - off] : 0;
        __syncthreads();
        sums[t] += v;
        __syncthreads();
    }
    int base = (t > 0) ? sums[t - 1] : 0;
#pragma unroll
    for (int j = 0; j < 10; j++) {
        int i = t * 10 + j;
        if (i < NN) {
            int off = base + loc[j];
            g_rowstart[i] = off;
            g_cursor[i]   = off;
        }
    }
    if (t == 1023) g_rowstart[NN] = sums[1023];
}

__global__ void k_scatter(const int* __restrict__ src, const int* __restrict__ dst,
                          const float* __restrict__ w, int E) {
    int e = blockIdx.x * blockDim.x + threadIdx.x;
    if (e < E) {
        int d = dst[e];
        int p = atomicAdd(&g_cursor[d], 1);
        ull cv = ((ull)__float_as_uint(w[e]) << 32) | (unsigned)src[e];
        g_cv[p] = cv;
    }
}

// ---------------------------------------------------------------
// gemm1: partial = x[:, kb*128:(kb+1)*128] @ W1[kb*128.., :]
// BM=64, BN=32, BK=32, 256 threads, 2x4 microtile, plain FFMA.
__global__ __launch_bounds__(256) void k_gemm1(const float* __restrict__ x,
                                               const float* __restrict__ W1) {
    __shared__ float xs[64][36];
    __shared__ float ws[32][36];
    const int tid = threadIdx.x;
    const int tx  = tid & 7;
    const int ty  = tid >> 3;
    const int row0 = blockIdx.x * 64;
    const int kbase = blockIdx.y * 128;
    float* outbuf = g_xw1p + (size_t)blockIdx.y * (NN * NH);

    float acc[2][4] = {};

    for (int kc = 0; kc < 4; kc++) {
        int k0 = kbase + kc * 32;
#pragma unroll
        for (int j = 0; j < 2; j++) {
            int f  = tid + 256 * j;
            int r  = f >> 3;
            int kq = f & 7;
            int gr = row0 + r;
            float4 v = make_float4(0.f, 0.f, 0.f, 0.f);
            if (gr < NN) v = *(const float4*)&x[(size_t)gr * NF + k0 + kq * 4];
            *(float4*)&xs[r][kq * 4] = v;
        }
        {
            int r  = tid >> 3;
            int kq = tid & 7;
            *(float4*)&ws[r][kq * 4] = *(const float4*)&W1[(k0 + r) * NH + kq * 4];
        }
        __syncthreads();
#pragma unroll
        for (int kk = 0; kk < 32; kk++) {
            float a0 = xs[ty * 2 + 0][kk];
            float a1 = xs[ty * 2 + 1][kk];
            float4 b = *(float4*)&ws[kk][tx * 4];
            acc[0][0] += a0 * b.x; acc[0][1] += a0 * b.y;
            acc[0][2] += a0 * b.z; acc[0][3] += a0 * b.w;
            acc[1][0] += a1 * b.x; acc[1][1] += a1 * b.y;
            acc[1][2] += a1 * b.z; acc[1][3] += a1 * b.w;
        }
        __syncthreads();
    }
#pragma unroll
    for (int i = 0; i < 2; i++) {
        int gr = row0 + ty * 2 + i;
        if (gr < NN) {
            float4 o = make_float4(acc[i][0], acc[i][1], acc[i][2], acc[i][3]);
            *(float4*)&outbuf[gr * NH + tx * 4] = o;
        }
    }
}

// sum the 4 K-chunk partials
__global__ void k_add() {
    int i = blockIdx.x * blockDim.x + threadIdx.x;
    if (i < NN * NH / 4) {
        float4 a = *(float4*)&g_xw1p[0 * NN * NH + i * 4];
        float4 b = *(float4*)&g_xw1p[1 * NN * NH + i * 4];
        float4 c = *(float4*)&g_xw1p[2 * NN * NH + i * 4];
        float4 d = *(float4*)&g_xw1p[3 * NN * NH + i * 4];
        float4 o = make_float4(a.x + b.x + c.x + d.x, a.y + b.y + c.y + d.y,
                               a.z + b.z + c.z + d.z, a.w + b.w + c.w + d.w);
        *(float4*)&g_xw1[i * 4] = o;
    }
}

// ---------------------------------------------------------------
// spmm1: h = relu(A_hat @ xw1). Warp per row; uniform packed cv loads.
__global__ void k_spmm1() {
    int warp = (blockIdx.x * blockDim.x + threadIdx.x) >> 5;
    int l = threadIdx.x & 31;
    if (warp >= NN) return;
    int start = g_rowstart[warp];
    int end   = g_rowstart[warp + 1];
    float acc = 0.f;
    int e = start;
    for (; e + 3 < end; e += 4) {
        ull cv0 = g_cv[e + 0], cv1 = g_cv[e + 1], cv2 = g_cv[e + 2], cv3 = g_cv[e + 3];
        int s0 = (int)(unsigned)cv0, s1 = (int)(unsigned)cv1;
        int s2 = (int)(unsigned)cv2, s3 = (int)(unsigned)cv3;
        float w0 = __uint_as_float((unsigned)(cv0 >> 32));
        float w1 = __uint_as_float((unsigned)(cv1 >> 32));
        float w2 = __uint_as_float((unsigned)(cv2 >> 32));
        float w3 = __uint_as_float((unsigned)(cv3 >> 32));
        acc += w0 * g_xw1[s0 * NH + l];
        acc += w1 * g_xw1[s1 * NH + l];
        acc += w2 * g_xw1[s2 * NH + l];
        acc += w3 * g_xw1[s3 * NH + l];
    }
    for (; e < end; e++) {
        ull cv = g_cv[e];
        int s = (int)(unsigned)cv;
        float w = __uint_as_float((unsigned)(cv >> 32));
        acc += w * g_xw1[s * NH + l];
    }
    g_h[warp * NH + l] = fmaxf(acc, 0.f);
}

// hw2 = h @ W2 (thread per row)
__global__ void k_gemm2(const float* __restrict__ W2) {
    __shared__ float w2s[NH * NC];
    const int tid = threadIdx.x;
    for (int i = tid; i < NH * NC; i += blockDim.x) w2s[i] = W2[i];
    __syncthreads();
    int row = blockIdx.x * blockDim.x + tid;
    if (row >= NN) return;
    float acc[NC] = {};
#pragma unroll
    for (int l = 0; l < NH; l++) {
        float hv = g_h[row * NH + l];
#pragma unroll
        for (int c = 0; c < NC; c++) acc[c] += hv * w2s[l * NC + c];
    }
#pragma unroll
    for (int q = 0; q < NC; q += 4) {
        float4 o = make_float4(acc[q], acc[q + 1], acc[q + 2], acc[q + 3]);
        *(float4*)&g_hw2[row * NC + q] = o;
    }
}

// spmm2: z = A_hat @ hw2. Warp per row; half-warps process alternating edges.
__global__ void k_spmm2() {
    int warp = (blockIdx.x * blockDim.x + threadIdx.x) >> 5;
    int l = threadIdx.x & 31;
    if (warp >= NN) return;
    int f    = l & 15;
    int half = l >> 4;
    int start = g_rowstart[warp];
    int end   = g_rowstart[warp + 1];
    float acc = 0.f;
    for (int e = start + half; e < end; e += 2) {
        ull cv = g_cv[e];
        int s = (int)(unsigned)cv;
        float w = __uint_as_float((unsigned)(cv >> 32));
        acc += w * g_hw2[s * NC + f];
    }
    acc += __shfl_xor_sync(0xffffffffu, acc, 16);
    if (l < 16) g_z[warp * NC + l] = acc;
}

// ---------------------------------------------------------------
// decode: out = sigmoid(z @ z^T), SYMMETRIC. Only upper-triangle 64x64 tiles
// (12403 blocks); each block writes its tile and (off-diagonal) the transpose.
// Both writes are float4 on 16B-aligned addresses -> full 32B-sector efficiency.
__global__ __launch_bounds__(256) void k_decode(float* __restrict__ out) {
    __shared__ float zr[NC][68];
    __shared__ float zc[NC][68];
    const int t = blockIdx.x;
    // triangular index: t = j*(j+1)/2 + i, i <= j
    int j = (int)((sqrtf(8.f * (float)t + 1.f) - 1.f) * 0.5f);
    while ((j + 1) * (j + 2) / 2 <= t) j++;
    while (j * (j + 1) / 2 > t) j--;
    const int i = t - j * (j + 1) / 2;
    const int r0 = i * 64;
    const int c0 = j * 64;
    const int tid = threadIdx.x;

    // load 64 rows (tile i) and 64 cols (tile j) of z, k-major
    {
        int row = tid >> 2;   // 0..63
        int kq  = tid & 3;
        int gr = r0 + row;
        float4 v = (gr < NN) ? *(const float4*)&g_z[gr * NC + kq * 4]
                             : make_float4(0.f, 0.f, 0.f, 0.f);
        zr[kq * 4 + 0][row] = v.x; zr[kq * 4 + 1][row] = v.y;
        zr[kq * 4 + 2][row] = v.z; zr[kq * 4 + 3][row] = v.w;
        int gc = c0 + row;
        float4 w = (gc < NN) ? *(const float4*)&g_z[gc * NC + kq * 4]
                             : make_float4(0.f, 0.f, 0.f, 0.f);
        zc[kq * 4 + 0][row] = w.x; zc[kq * 4 + 1][row] = w.y;
        zc[kq * 4 + 2][row] = w.z; zc[kq * 4 + 3][row] = w.w;
    }
    __syncthreads();

    const int tx = tid & 15;   // 16 col groups of 4
    const int ty = tid >> 4;   // 16 row groups of 4

    float acc[4][4] = {};
#pragma unroll
    for (int k = 0; k < NC; k++) {
        float4 a = *(float4*)&zr[k][ty * 4];
        float4 b = *(float4*)&zc[k][tx * 4];
        acc[0][0] += a.x * b.x; acc[0][1] += a.x * b.y; acc[0][2] += a.x * b.z; acc[0][3] += a.x * b.w;
        acc[1][0] += a.y * b.x; acc[1][1] += a.y * b.y; acc[1][2] += a.y * b.z; acc[1][3] += a.y * b.w;
        acc[2][0] += a.z * b.x; acc[2][1] += a.z * b.y; acc[2][2] += a.z * b.z; acc[2][3] += a.z * b.w;
        acc[3][0] += a.w * b.x; acc[3][1] += a.w * b.y; acc[3][2] += a.w * b.z; acc[3][3] += a.w * b.w;
    }

    // sigmoid once; reuse for both writes
    float s[4][4];
#pragma unroll
    for (int p = 0; p < 4; p++)
#pragma unroll
        for (int q = 0; q < 4; q++) s[p][q] = sigmoidf(acc[p][q]);

    // direct tile: rows r0+ty*4+p, cols c0+tx*4.. (NN % 4 == 0, so base<NN => base+3<NN)
    const int gcb = c0 + tx * 4;
    if (gcb < NN) {
#pragma unroll
        for (int p = 0; p < 4; p++) {
            int gr = r0 + ty * 4 + p;
            if (gr < NN) {
                float4 o = make_float4(s[p][0], s[p][1], s[p][2], s[p][3]);
                *(float4*)&out[(size_t)gr * NN + gcb] = o;
            }
        }
    }

    // transposed tile (skip on diagonal): rows c0+tx*4+q, cols r0+ty*4..
    if (i != j) {
        const int grb = r0 + ty * 4;
        if (grb < NN) {
#pragma unroll
            for (int q = 0; q < 4; q++) {
                int gc = c0 + tx * 4 + q;
                if (gc < NN) {
                    float4 o = make_float4(s[0][q], s[1][q], s[2][q], s[3][q]);
                    *(float4*)&out[(size_t)gc * NN + grb] = o;
                }
            }
        }
    }
}

// ---------------------------------------------------------------
extern "C" void kernel_launch(void* const* d_in, const int* in_sizes, int n_in,
                              void* d_out, int out_size) {
    const float* x   = (const float*)d_in[0];   // [10000, 512]
    const float* W1  = (const float*)d_in[1];   // [512, 32]
    const float* W2  = (const float*)d_in[2];   // [32, 16]
    const float* ew  = (const float*)d_in[3];   // [E]
    const int*   src = (const int*)d_in[4];     // [E]
    const int*   dst = (const int*)d_in[5];     // [E]
    float* out = (float*)d_out;
    const int E = in_sizes[3];

    const int eb = (E + 255) / 256;

    k_init_counts<<<(NN + 255) / 256, 256>>>();
    k_hist<<<eb, 256>>>(dst, E);
    k_scan<<<1, 1024>>>();
    k_scatter<<<eb, 256>>>(src, dst, ew, E);

    dim3 g1((NN + 63) / 64, 4);
    k_gemm1<<<g1, 256>>>(x, W1);
    k_add<<<(NN * NH / 4 + 255) / 256, 256>>>();
    k_spmm1<<<(NN * 32 + 255) / 256, 256>>>();
    k_gemm2<<<(NN + 255) / 256, 256>>>(W2);
    k_spmm2<<<(NN * 32 + 255) / 256, 256>>>();

    k_decode<<<NTRI, 256>>>(out);
}